// round 13
// baseline (speedup 1.0000x reference)
#include <cuda_runtime.h>
#include <cuda_fp16.h>
#include <math.h>
#include <stdint.h>

// ---------------------------------------------------------------------------
// ArcMarginProduct constants (S=30, M=0.5)
// ---------------------------------------------------------------------------
#define S_SCALE   30.0f
#define INV_S     (1.0f / 30.0f)
#define COS_M_C   0.87758256189037271612f   // cos(0.5)
#define SIN_M_C   0.47942553860420300027f   // sin(0.5)
#define TH_C     (-0.87758256189037271612f) // cos(pi - 0.5)
#define MM_C      7.19138307906304500405f   // S * sin(0.5) * 0.5

#define MAXB  1024
#define CPAD  100096     // 391 * 256; pad rows stay zero (zero-init statics)
#define DFIX  512
#define NYMAX 1024
#define LOOKAHEAD 64     // groups; > max groups resident per wave (37)

// fp16, normalization-folded operands
__device__ __align__(256) __half g_Ah[MAXB * DFIX];   // S * a / ||a||
__device__ __align__(256) __half g_Wh[CPAD * DFIX];   // w / ||w||
__device__ unsigned g_cnt[NYMAX];                     // per-group arrive counters

// ---------------------------------------------------------------------------
// Fused prep kernel: block roles by blockIdx.x
//   [0, B)                : A rows  (smul = S)
//   [B, B+upfront)        : W rows  (smul = 1)
//   last block            : reset g_cnt
// ---------------------------------------------------------------------------
__global__ void prep_kernel(const float* __restrict__ A, const float* __restrict__ W,
                            int B, int upfront, int ny, int D)
{
    int bid = blockIdx.x;
    if (bid >= B + upfront) {                  // flags reset
        for (int i = threadIdx.x; i < ny; i += blockDim.x) g_cnt[i] = 0u;
        return;
    }
    const float* x;
    __half* dst;
    float smul;
    int row;
    if (bid < B) { row = bid;      x = A; dst = g_Ah; smul = S_SCALE; }
    else         { row = bid - B;  x = W; dst = g_Wh; smul = 1.0f;    }

    const float4* xv = reinterpret_cast<const float4*>(x + (size_t)row * (size_t)D);
    float4 v = xv[threadIdx.x];

    float s = v.x * v.x + v.y * v.y + v.z * v.z + v.w * v.w;
    #pragma unroll
    for (int off = 16; off > 0; off >>= 1)
        s += __shfl_down_sync(0xffffffffu, s, off);

    __shared__ float wsum[4];
    __shared__ float s_sc;
    int lane = threadIdx.x & 31, wid = threadIdx.x >> 5;
    if (lane == 0) wsum[wid] = s;
    __syncthreads();
    if (threadIdx.x == 0) {
        float t = wsum[0] + wsum[1] + wsum[2] + wsum[3];
        s_sc = smul / fmaxf(sqrtf(t), 1e-12f);
    }
    __syncthreads();
    float sc = s_sc;

    __half2 h01 = __floats2half2_rn(v.x * sc, v.y * sc);
    __half2 h23 = __floats2half2_rn(v.z * sc, v.w * sc);
    __half2* p = reinterpret_cast<__half2*>(dst + (size_t)row * (size_t)D) + threadIdx.x * 2;
    p[0] = h01;
    p[1] = h23;
}

// ---------------------------------------------------------------------------
// fp16 tensor-core GEMM, fp16-ACCUMULATE MMA with per-chunk fp32 promotion.
//   CTA 128x128, BK=64, 8 warps (2m x 4n), warp tile 64x32 processed in two
//   32x32 halves (8 fp16-acc tiles live at a time -> fits 128 regs, 2 CTA/SM).
//   Look-ahead W conversion + fused margin fixup in the epilogue.
// ---------------------------------------------------------------------------
#define BM 128
#define BN 128
#define BK 64
#define NTHREADS 256
#define A_TILE_BYTES (BM * 128)                      // 16384
#define B_TILE_BYTES (BN * 128)                      // 16384
#define STAGE_BYTES  (A_TILE_BYTES + B_TILE_BYTES)   // 32768
#define NSTAGE 3
#define SMEM_BYTES (NSTAGE * STAGE_BYTES)            // 98304

// fp16-accumulate MMA, accumulating into (c0,c1)
__device__ __forceinline__ void mma_h16(uint32_t& c0, uint32_t& c1,
                                        const uint32_t* a, uint32_t b0, uint32_t b1) {
    asm volatile(
        "mma.sync.aligned.m16n8k16.row.col.f16.f16.f16.f16 "
        "{%0,%1}, {%2,%3,%4,%5}, {%6,%7}, {%0,%1};"
        : "+r"(c0), "+r"(c1)
        : "r"(a[0]), "r"(a[1]), "r"(a[2]), "r"(a[3]), "r"(b0), "r"(b1));
}
// fp16-accumulate MMA with zero initial accumulator (first k-step of a chunk)
__device__ __forceinline__ void mma_h16z(uint32_t& c0, uint32_t& c1,
                                         const uint32_t* a, uint32_t b0, uint32_t b1) {
    asm volatile(
        "mma.sync.aligned.m16n8k16.row.col.f16.f16.f16.f16 "
        "{%0,%1}, {%2,%3,%4,%5}, {%6,%7}, {%8,%8};"
        : "=r"(c0), "=r"(c1)
        : "r"(a[0]), "r"(a[1]), "r"(a[2]), "r"(a[3]), "r"(b0), "r"(b1), "r"(0u));
}

#define LDMATRIX_X4(r0, r1, r2, r3, addr)                                   \
    asm volatile("ldmatrix.sync.aligned.m8n8.x4.shared.b16 "                \
                 "{%0,%1,%2,%3}, [%4];"                                     \
                 : "=r"(r0), "=r"(r1), "=r"(r2), "=r"(r3) : "r"(addr))

__device__ __forceinline__ void cp_async16(uint32_t sm_dst, const void* g_src) {
    asm volatile("cp.async.cg.shared.global [%0], [%1], 16;"
                 :: "r"(sm_dst), "l"(g_src));
}

__global__ void __launch_bounds__(NTHREADS, 2)
arc_gemm_f16(const float* __restrict__ W, const int* __restrict__ label,
             float* __restrict__ out, int C, int D, int ny, int B)
{
    extern __shared__ char sm[];
    const uint32_t smaddr = (uint32_t)__cvta_generic_to_shared(sm);
    __shared__ int s_nfix;
    __shared__ int s_fixb[8];
    __shared__ int s_fixc[8];

    const int tid  = threadIdx.x;
    const int lane = tid & 31;
    const int warp = tid >> 5;
    const int y    = blockIdx.y;
    const int b0   = blockIdx.x * BM;
    const int c0   = y * BN;

    // ---- look-ahead W conversion: 16 rows of group y+LOOKAHEAD ----
    {
        int yt = y + LOOKAHEAD;
        if (yt < ny) {
            int rr = yt * BN + (int)blockIdx.x * 16 + (tid >> 4);
            int seg = tid & 15;
            if (rr < C) {
                const float4* src =
                    reinterpret_cast<const float4*>(W + (size_t)rr * (size_t)D);
                float4 v[8];
                #pragma unroll
                for (int q = 0; q < 8; q++) v[q] = src[seg + q * 16];
                float s = 0.0f;
                #pragma unroll
                for (int q = 0; q < 8; q++)
                    s += v[q].x * v[q].x + v[q].y * v[q].y
                       + v[q].z * v[q].z + v[q].w * v[q].w;
                #pragma unroll
                for (int off = 8; off > 0; off >>= 1)
                    s += __shfl_xor_sync(0xffffffffu, s, off);
                float rn = 1.0f / fmaxf(sqrtf(s), 1e-12f);
                uint2* dst = reinterpret_cast<uint2*>(g_Wh + (size_t)rr * (size_t)D);
                #pragma unroll
                for (int q = 0; q < 8; q++) {
                    __half2 h0 = __floats2half2_rn(v[q].x * rn, v[q].y * rn);
                    __half2 h1 = __floats2half2_rn(v[q].z * rn, v[q].w * rn);
                    uint2 u;
                    u.x = *reinterpret_cast<uint32_t*>(&h0);
                    u.y = *reinterpret_cast<uint32_t*>(&h1);
                    dst[seg + q * 16] = u;
                }
            }
            __syncthreads();
            if (tid == 0)
                asm volatile("red.release.gpu.global.add.u32 [%0], %1;"
                             :: "l"(&g_cnt[yt]), "r"(1u) : "memory");
        }
        if (y >= LOOKAHEAD) {
            if (tid == 0) {
                unsigned v = 0;
                do {
                    asm volatile("ld.acquire.gpu.global.u32 %0, [%1];"
                                 : "=r"(v) : "l"(&g_cnt[y]) : "memory");
                    if (v != 8u) __nanosleep(128);
                } while (v != 8u);
            }
            __syncthreads();
        }
    }

    // ---- GEMM body ----
    const int wm = (warp >> 2) * 64;   // 0, 64
    const int wn = (warp & 3) * 32;    // 0, 32, 64, 96
    const int r = lane >> 2;           // 0..7
    const int c = lane & 3;            // 0..3

    float acc[4][4][4];
    #pragma unroll
    for (int mi = 0; mi < 4; mi++)
        #pragma unroll
        for (int ni = 0; ni < 4; ni++)
            #pragma unroll
            for (int j = 0; j < 4; j++)
                acc[mi][ni][j] = 0.0f;

    const int nch = D / BK;   // 8

    // --- strength-reduced loader state ---
    const int rowL = tid >> 3;
    const int segL = tid & 7;
    const uint32_t swzL = (((uint32_t)segL << 4) ^ (((uint32_t)rowL & 7) << 4));
    const uint32_t smoffA = (uint32_t)rowL * 128 + swzL;
    const uint32_t smoffB = A_TILE_BYTES + smoffA;
    const char* gA = (const char*)g_Ah + (size_t)(b0 + rowL) * 1024 + segL * 16;
    const char* gB = (const char*)g_Wh + (size_t)(c0 + rowL) * 1024 + segL * 16;

    auto load_chunk = [&](int ch, int st) {
        uint32_t stage = smaddr + st * STAGE_BYTES;
        const char* ga = gA + ch * 128;
        uint32_t sa = stage + smoffA;
        #pragma unroll
        for (int h = 0; h < 4; h++) {
            cp_async16(sa, ga);
            sa += 32 * 128;
            ga += 32 * 1024;
        }
        const char* gb = gB + ch * 128;
        uint32_t sb = stage + smoffB;
        #pragma unroll
        for (int h = 0; h < 4; h++) {
            cp_async16(sb, gb);
            sb += 32 * 128;
            gb += 32 * 1024;
        }
        asm volatile("cp.async.commit_group;" ::: "memory");
    };

    // ldmatrix per-thread addressing (SW128 swizzle)
    const int lane15 = lane & 15;
    const uint32_t kq16 = ((lane >> 4) & 1) << 4;
    const uint32_t sw = (uint32_t)(lane15 & 7) << 4;
    uint32_t relA[4], relB[2];
    #pragma unroll
    for (int t = 0; t < 4; t++)
        relA[t] = (uint32_t)(wm + t * 16 + lane15) * 128;
    #pragma unroll
    for (int t = 0; t < 2; t++)
        relB[t] = A_TILE_BYTES + (uint32_t)(wn + t * 16 + lane15) * 128;

    load_chunk(0, 0);
    load_chunk(1, 1);

    for (int i = 0; i < nch; i++) {
        if (i + 1 < nch)
            asm volatile("cp.async.wait_group 1;" ::: "memory");
        else
            asm volatile("cp.async.wait_group 0;" ::: "memory");
        __syncthreads();

        if (i + 2 < nch)
            load_chunk(i + 2, (i + 2) % NSTAGE);

        uint32_t stage = smaddr + (i % NSTAGE) * STAGE_BYTES;

        // Two mt-halves; fp16 accumulate across the 4 k-steps of this chunk,
        // then promote into fp32 accumulators.
        #pragma unroll
        for (int half = 0; half < 2; half++) {
            uint32_t hacc[8][2];   // [mt2*4 + nt*2 + j][2 regs]

            #pragma unroll
            for (int ks = 0; ks < 4; ks++) {
                uint32_t kx = (((uint32_t)ks << 5) + kq16) ^ sw;

                uint32_t af[2][4];
                #pragma unroll
                for (int mt2 = 0; mt2 < 2; mt2++)
                    LDMATRIX_X4(af[mt2][0], af[mt2][1], af[mt2][2], af[mt2][3],
                                stage + relA[half * 2 + mt2] + kx);

                uint32_t bf[2][4];
                #pragma unroll
                for (int nt = 0; nt < 2; nt++)
                    LDMATRIX_X4(bf[nt][0], bf[nt][1], bf[nt][2], bf[nt][3],
                                stage + relB[nt] + kx);

                #pragma unroll
                for (int mt2 = 0; mt2 < 2; mt2++)
                    #pragma unroll
                    for (int nt = 0; nt < 2; nt++) {
                        int t0 = mt2 * 4 + nt * 2;
                        if (ks == 0) {
                            mma_h16z(hacc[t0][0], hacc[t0][1], af[mt2],
                                     bf[nt][0], bf[nt][2]);
                            mma_h16z(hacc[t0 + 1][0], hacc[t0 + 1][1], af[mt2],
                                     bf[nt][1], bf[nt][3]);
                        } else {
                            mma_h16(hacc[t0][0], hacc[t0][1], af[mt2],
                                    bf[nt][0], bf[nt][2]);
                            mma_h16(hacc[t0 + 1][0], hacc[t0 + 1][1], af[mt2],
                                    bf[nt][1], bf[nt][3]);
                        }
                    }
            }

            // promote fp16 chunk sums into fp32 accumulators
            #pragma unroll
            for (int mt2 = 0; mt2 < 2; mt2++)
                #pragma unroll
                for (int nj = 0; nj < 4; nj++) {
                    int t = mt2 * 4 + nj;
                    float* a4 = acc[half * 2 + mt2][nj];
                    float2 f0 = __half22float2(
                        *reinterpret_cast<__half2*>(&hacc[t][0]));
                    float2 f1 = __half22float2(
                        *reinterpret_cast<__half2*>(&hacc[t][1]));
                    a4[0] += f0.x;
                    a4[1] += f0.y;
                    a4[2] += f1.x;
                    a4[3] += f1.y;
                }
        }
        __syncthreads();
    }

    // ---- fused margin fixup: collect label hits for this tile ----
    if (tid == 0) s_nfix = 0;
    __syncthreads();
    {
        int b = b0 + tid;
        if (tid < BM && b < B) {
            int lab = label[b];
            if (lab >= c0 && lab < c0 + BN) {
                int slot = atomicAdd(&s_nfix, 1);
                if (slot < 8) { s_fixb[slot] = b; s_fixc[slot] = lab; }
            }
        }
    }
    __syncthreads();
    const int nfix = s_nfix;

    // epilogue: bare stores + inline margin at label positions
    #pragma unroll
    for (int ni = 0; ni < 4; ni++) {
        int cc = c0 + wn + ni * 8 + 2 * c;
        if (cc < C) {
            #pragma unroll
            for (int mi = 0; mi < 4; mi++) {
                #pragma unroll
                for (int h = 0; h < 2; h++) {
                    int row = b0 + wm + mi * 16 + h * 8 + r;
                    float2 v = make_float2(acc[mi][ni][h * 2 + 0],
                                           acc[mi][ni][h * 2 + 1]);
                    if (nfix) {
                        for (int e = 0; e < nfix && e < 8; e++) {
                            if (s_fixb[e] == row) {
                                int fc = s_fixc[e];
                                if (fc == cc || fc == cc + 1) {
                                    float* pv = (fc == cc) ? &v.x : &v.y;
                                    float cosv = *pv * INV_S;
                                    float s2 = 1.0f - cosv * cosv;
                                    s2 = fminf(fmaxf(s2, 0.0f), 1.0f);
                                    float phi = cosv * COS_M_C - sqrtf(s2) * SIN_M_C;
                                    phi = (cosv > TH_C) ? phi : (cosv - MM_C);
                                    *pv = phi * S_SCALE;
                                }
                            }
                        }
                    }
                    *reinterpret_cast<float2*>(out + (size_t)row * (size_t)C + cc) = v;
                }
            }
        }
    }
}

// ---------------------------------------------------------------------------
// Launch
// ---------------------------------------------------------------------------
extern "C" void kernel_launch(void* const* d_in, const int* in_sizes, int n_in,
                              void* d_out, int out_size)
{
    const float* input  = (const float*)d_in[0];   // [B, D]
    const int*   label  = (const int*)  d_in[1];   // [B]
    const float* weight = (const float*)d_in[2];   // [C, D]
    float* out = (float*)d_out;                    // [B, C]

    const int B = in_sizes[1];
    const int D = in_sizes[0] / B;
    const int C = in_sizes[2] / D;
    const int ny = (C + BN - 1) / BN;

    cudaFuncSetAttribute(arc_gemm_f16, cudaFuncAttributeMaxDynamicSharedMemorySize,
                         SMEM_BYTES);

    int upfront = LOOKAHEAD * BN;
    if (upfront > C) upfront = C;

    // 1) fused prep: flags reset + A rows + upfront W rows (one launch)
    prep_kernel<<<B + upfront + 1, 128>>>(input, weight, B, upfront, ny, D);

    // 2) GEMM with look-ahead W conversion + fused margin epilogue
    dim3 grid(B / BM, ny);
    arc_gemm_f16<<<grid, NTHREADS, SMEM_BYTES>>>(weight, label, out, C, D, ny, B);
}

// round 14
// speedup vs baseline: 1.1369x; 1.1369x over previous
#include <cuda_runtime.h>
#include <cuda_fp16.h>
#include <math.h>
#include <stdint.h>

// ---------------------------------------------------------------------------
// ArcMarginProduct constants (S=30, M=0.5)
// ---------------------------------------------------------------------------
#define S_SCALE   30.0f
#define INV_S     (1.0f / 30.0f)
#define COS_M_C   0.87758256189037271612f   // cos(0.5)
#define SIN_M_C   0.47942553860420300027f   // sin(0.5)
#define TH_C     (-0.87758256189037271612f) // cos(pi - 0.5)
#define MM_C      7.19138307906304500405f   // S * sin(0.5) * 0.5

#define MAXB  1024
#define CPAD  100096     // 391 * 256; pad rows stay zero (zero-init statics)
#define DFIX  512
#define NYMAX 1024
#define LOOKAHEAD 64     // groups; > max groups resident per wave (37)

// fp16, normalization-folded operands
__device__ __align__(256) __half g_Ah[MAXB * DFIX];   // S * a / ||a||
__device__ __align__(256) __half g_Wh[CPAD * DFIX];   // w / ||w||
__device__ unsigned g_cnt[NYMAX];                     // per-group arrive counters

// ---------------------------------------------------------------------------
// Fused prep kernel: block roles by blockIdx.x
//   [0, B)          : A rows  (smul = S)
//   [B, B+upfront)  : W rows  (smul = 1)
//   last block      : reset g_cnt
// ---------------------------------------------------------------------------
__global__ void prep_kernel(const float* __restrict__ A, const float* __restrict__ W,
                            int B, int upfront, int ny, int D)
{
    int bid = blockIdx.x;
    if (bid >= B + upfront) {                  // flags reset
        for (int i = threadIdx.x; i < ny; i += blockDim.x) g_cnt[i] = 0u;
        return;
    }
    const float* x;
    __half* dst;
    float smul;
    int row;
    if (bid < B) { row = bid;      x = A; dst = g_Ah; smul = S_SCALE; }
    else         { row = bid - B;  x = W; dst = g_Wh; smul = 1.0f;    }

    const float4* xv = reinterpret_cast<const float4*>(x + (size_t)row * (size_t)D);
    float4 v = xv[threadIdx.x];

    float s = v.x * v.x + v.y * v.y + v.z * v.z + v.w * v.w;
    #pragma unroll
    for (int off = 16; off > 0; off >>= 1)
        s += __shfl_down_sync(0xffffffffu, s, off);

    __shared__ float wsum[4];
    __shared__ float s_sc;
    int lane = threadIdx.x & 31, wid = threadIdx.x >> 5;
    if (lane == 0) wsum[wid] = s;
    __syncthreads();
    if (threadIdx.x == 0) {
        float t = wsum[0] + wsum[1] + wsum[2] + wsum[3];
        s_sc = smul / fmaxf(sqrtf(t), 1e-12f);
    }
    __syncthreads();
    float sc = s_sc;

    __half2 h01 = __floats2half2_rn(v.x * sc, v.y * sc);
    __half2 h23 = __floats2half2_rn(v.z * sc, v.w * sc);
    __half2* p = reinterpret_cast<__half2*>(dst + (size_t)row * (size_t)D) + threadIdx.x * 2;
    p[0] = h01;
    p[1] = h23;
}

// ---------------------------------------------------------------------------
// fp16 tensor-core GEMM (fp32 accumulate) + look-ahead W conversion +
// fused margin fixup in the epilogue.
// GEMM: CTA 128x128, BK=64, 8 warps (2m x 4n), warp tile 64x32, 2 CTAs/SM,
//   SW128 XOR swizzle + ldmatrix, 3-stage cp.async pipeline,
//   strength-reduced loader (round-10 body — best measured config).
// ---------------------------------------------------------------------------
#define BM 128
#define BN 128
#define BK 64
#define NTHREADS 256
#define A_TILE_BYTES (BM * 128)                      // 16384
#define B_TILE_BYTES (BN * 128)                      // 16384
#define STAGE_BYTES  (A_TILE_BYTES + B_TILE_BYTES)   // 32768
#define NSTAGE 3
#define SMEM_BYTES (NSTAGE * STAGE_BYTES)            // 98304

__device__ __forceinline__ void mma_f16(float* d, const uint32_t* a,
                                        uint32_t b0, uint32_t b1) {
    asm volatile(
        "mma.sync.aligned.m16n8k16.row.col.f32.f16.f16.f32 "
        "{%0,%1,%2,%3}, {%4,%5,%6,%7}, {%8,%9}, {%0,%1,%2,%3};"
        : "+f"(d[0]), "+f"(d[1]), "+f"(d[2]), "+f"(d[3])
        : "r"(a[0]), "r"(a[1]), "r"(a[2]), "r"(a[3]), "r"(b0), "r"(b1));
}

#define LDMATRIX_X4(r0, r1, r2, r3, addr)                                   \
    asm volatile("ldmatrix.sync.aligned.m8n8.x4.shared.b16 "                \
                 "{%0,%1,%2,%3}, [%4];"                                     \
                 : "=r"(r0), "=r"(r1), "=r"(r2), "=r"(r3) : "r"(addr))

__device__ __forceinline__ void cp_async16(uint32_t sm_dst, const void* g_src) {
    asm volatile("cp.async.cg.shared.global [%0], [%1], 16;"
                 :: "r"(sm_dst), "l"(g_src));
}

__global__ void __launch_bounds__(NTHREADS, 2)
arc_gemm_f16(const float* __restrict__ W, const int* __restrict__ label,
             float* __restrict__ out, int C, int D, int ny, int B)
{
    extern __shared__ char sm[];
    const uint32_t smaddr = (uint32_t)__cvta_generic_to_shared(sm);
    __shared__ int s_nfix;
    __shared__ int s_fixb[8];
    __shared__ int s_fixc[8];

    const int tid  = threadIdx.x;
    const int lane = tid & 31;
    const int warp = tid >> 5;
    const int y    = blockIdx.y;
    const int b0   = blockIdx.x * BM;
    const int c0   = y * BN;

    // ---- look-ahead W conversion: 16 rows of group y+LOOKAHEAD ----
    {
        int yt = y + LOOKAHEAD;
        if (yt < ny) {
            int rr = yt * BN + (int)blockIdx.x * 16 + (tid >> 4);
            int seg = tid & 15;
            if (rr < C) {
                const float4* src =
                    reinterpret_cast<const float4*>(W + (size_t)rr * (size_t)D);
                float4 v[8];
                #pragma unroll
                for (int q = 0; q < 8; q++) v[q] = src[seg + q * 16];
                float s = 0.0f;
                #pragma unroll
                for (int q = 0; q < 8; q++)
                    s += v[q].x * v[q].x + v[q].y * v[q].y
                       + v[q].z * v[q].z + v[q].w * v[q].w;
                #pragma unroll
                for (int off = 8; off > 0; off >>= 1)
                    s += __shfl_xor_sync(0xffffffffu, s, off);
                float rn = 1.0f / fmaxf(sqrtf(s), 1e-12f);
                uint2* dst = reinterpret_cast<uint2*>(g_Wh + (size_t)rr * (size_t)D);
                #pragma unroll
                for (int q = 0; q < 8; q++) {
                    __half2 h0 = __floats2half2_rn(v[q].x * rn, v[q].y * rn);
                    __half2 h1 = __floats2half2_rn(v[q].z * rn, v[q].w * rn);
                    uint2 u;
                    u.x = *reinterpret_cast<uint32_t*>(&h0);
                    u.y = *reinterpret_cast<uint32_t*>(&h1);
                    dst[seg + q * 16] = u;
                }
            }
            __syncthreads();
            if (tid == 0)
                asm volatile("red.release.gpu.global.add.u32 [%0], %1;"
                             :: "l"(&g_cnt[yt]), "r"(1u) : "memory");
        }
        if (y >= LOOKAHEAD) {
            if (tid == 0) {
                unsigned v = 0;
                do {
                    asm volatile("ld.acquire.gpu.global.u32 %0, [%1];"
                                 : "=r"(v) : "l"(&g_cnt[y]) : "memory");
                    if (v != 8u) __nanosleep(128);
                } while (v != 8u);
            }
            __syncthreads();
        }
    }

    // ---- GEMM body (round-10 config, fp32 accumulate) ----
    const int wm = (warp >> 2) * 64;   // 0, 64
    const int wn = (warp & 3) * 32;    // 0, 32, 64, 96
    const int r = lane >> 2;           // 0..7
    const int c = lane & 3;            // 0..3

    float acc[4][4][4];
    #pragma unroll
    for (int mi = 0; mi < 4; mi++)
        #pragma unroll
        for (int ni = 0; ni < 4; ni++)
            #pragma unroll
            for (int j = 0; j < 4; j++)
                acc[mi][ni][j] = 0.0f;

    const int nch = D / BK;   // 8

    // --- strength-reduced loader state ---
    const int rowL = tid >> 3;
    const int segL = tid & 7;
    const uint32_t swzL = (((uint32_t)segL << 4) ^ (((uint32_t)rowL & 7) << 4));
    const uint32_t smoffA = (uint32_t)rowL * 128 + swzL;
    const uint32_t smoffB = A_TILE_BYTES + smoffA;
    const char* gA = (const char*)g_Ah + (size_t)(b0 + rowL) * 1024 + segL * 16;
    const char* gB = (const char*)g_Wh + (size_t)(c0 + rowL) * 1024 + segL * 16;

    auto load_chunk = [&](int ch, int st) {
        uint32_t stage = smaddr + st * STAGE_BYTES;
        const char* ga = gA + ch * 128;
        uint32_t sa = stage + smoffA;
        #pragma unroll
        for (int h = 0; h < 4; h++) {
            cp_async16(sa, ga);
            sa += 32 * 128;
            ga += 32 * 1024;
        }
        const char* gb = gB + ch * 128;
        uint32_t sb = stage + smoffB;
        #pragma unroll
        for (int h = 0; h < 4; h++) {
            cp_async16(sb, gb);
            sb += 32 * 128;
            gb += 32 * 1024;
        }
        asm volatile("cp.async.commit_group;" ::: "memory");
    };

    // ldmatrix per-thread addressing (SW128 swizzle)
    const int lane15 = lane & 15;
    const uint32_t kq16 = ((lane >> 4) & 1) << 4;
    const uint32_t sw = (uint32_t)(lane15 & 7) << 4;
    uint32_t relA[4], relB[2];
    #pragma unroll
    for (int t = 0; t < 4; t++)
        relA[t] = (uint32_t)(wm + t * 16 + lane15) * 128;
    #pragma unroll
    for (int t = 0; t < 2; t++)
        relB[t] = A_TILE_BYTES + (uint32_t)(wn + t * 16 + lane15) * 128;

    load_chunk(0, 0);
    load_chunk(1, 1);

    for (int i = 0; i < nch; i++) {
        if (i + 1 < nch)
            asm volatile("cp.async.wait_group 1;" ::: "memory");
        else
            asm volatile("cp.async.wait_group 0;" ::: "memory");
        __syncthreads();

        if (i + 2 < nch)
            load_chunk(i + 2, (i + 2) % NSTAGE);

        uint32_t stage = smaddr + (i % NSTAGE) * STAGE_BYTES;

        #pragma unroll
        for (int ks = 0; ks < 4; ks++) {
            uint32_t kx = (((uint32_t)ks << 5) + kq16) ^ sw;

            uint32_t af[4][4];
            #pragma unroll
            for (int mt = 0; mt < 4; mt++)
                LDMATRIX_X4(af[mt][0], af[mt][1], af[mt][2], af[mt][3],
                            stage + relA[mt] + kx);

            uint32_t bf[2][4];
            #pragma unroll
            for (int nt = 0; nt < 2; nt++)
                LDMATRIX_X4(bf[nt][0], bf[nt][1], bf[nt][2], bf[nt][3],
                            stage + relB[nt] + kx);

            #pragma unroll
            for (int mt = 0; mt < 4; mt++)
                #pragma unroll
                for (int nt = 0; nt < 2; nt++) {
                    mma_f16(acc[mt][nt * 2 + 0], af[mt], bf[nt][0], bf[nt][2]);
                    mma_f16(acc[mt][nt * 2 + 1], af[mt], bf[nt][1], bf[nt][3]);
                }
        }
        __syncthreads();
    }

    // ---- fused margin fixup: collect label hits for this tile ----
    if (tid == 0) s_nfix = 0;
    __syncthreads();
    {
        int b = b0 + tid;
        if (tid < BM && b < B) {
            int lab = label[b];
            if (lab >= c0 && lab < c0 + BN) {
                int slot = atomicAdd(&s_nfix, 1);
                if (slot < 8) { s_fixb[slot] = b; s_fixc[slot] = lab; }
            }
        }
    }
    __syncthreads();
    const int nfix = s_nfix;

    // epilogue: bare stores + inline margin at label positions
    #pragma unroll
    for (int ni = 0; ni < 4; ni++) {
        int cc = c0 + wn + ni * 8 + 2 * c;
        if (cc < C) {
            #pragma unroll
            for (int mi = 0; mi < 4; mi++) {
                #pragma unroll
                for (int h = 0; h < 2; h++) {
                    int row = b0 + wm + mi * 16 + h * 8 + r;
                    float2 v = make_float2(acc[mi][ni][h * 2 + 0],
                                           acc[mi][ni][h * 2 + 1]);
                    if (nfix) {
                        for (int e = 0; e < nfix && e < 8; e++) {
                            if (s_fixb[e] == row) {
                                int fc = s_fixc[e];
                                if (fc == cc || fc == cc + 1) {
                                    float* pv = (fc == cc) ? &v.x : &v.y;
                                    float cosv = *pv * INV_S;
                                    float s2 = 1.0f - cosv * cosv;
                                    s2 = fminf(fmaxf(s2, 0.0f), 1.0f);
                                    float phi = cosv * COS_M_C - sqrtf(s2) * SIN_M_C;
                                    phi = (cosv > TH_C) ? phi : (cosv - MM_C);
                                    *pv = phi * S_SCALE;
                                }
                            }
                        }
                    }
                    *reinterpret_cast<float2*>(out + (size_t)row * (size_t)C + cc) = v;
                }
            }
        }
    }
}

// ---------------------------------------------------------------------------
// Launch
// ---------------------------------------------------------------------------
extern "C" void kernel_launch(void* const* d_in, const int* in_sizes, int n_in,
                              void* d_out, int out_size)
{
    const float* input  = (const float*)d_in[0];   // [B, D]
    const int*   label  = (const int*)  d_in[1];   // [B]
    const float* weight = (const float*)d_in[2];   // [C, D]
    float* out = (float*)d_out;                    // [B, C]

    const int B = in_sizes[1];
    const int D = in_sizes[0] / B;
    const int C = in_sizes[2] / D;
    const int ny = (C + BN - 1) / BN;

    cudaFuncSetAttribute(arc_gemm_f16, cudaFuncAttributeMaxDynamicSharedMemorySize,
                         SMEM_BYTES);

    int upfront = LOOKAHEAD * BN;
    if (upfront > C) upfront = C;

    // 1) fused prep: flags reset + A rows + upfront W rows (one launch)
    prep_kernel<<<B + upfront + 1, 128>>>(input, weight, B, upfront, ny, D);

    // 2) GEMM with look-ahead W conversion + fused margin epilogue
    dim3 grid(B / BM, ny);
    arc_gemm_f16<<<grid, NTHREADS, SMEM_BYTES>>>(weight, label, out, C, D, ny, B);
}

// round 15
// speedup vs baseline: 1.5366x; 1.3515x over previous
#include <cuda_runtime.h>
#include <cuda_fp16.h>
#include <math.h>
#include <stdint.h>

// ---------------------------------------------------------------------------
// ArcMarginProduct constants (S=30, M=0.5)
// ---------------------------------------------------------------------------
#define S_SCALE   30.0f
#define INV_S     (1.0f / 30.0f)
#define COS_M_C   0.87758256189037271612f   // cos(0.5)
#define SIN_M_C   0.47942553860420300027f   // sin(0.5)
#define TH_C     (-0.87758256189037271612f) // cos(pi - 0.5)
#define MM_C      7.19138307906304500405f   // S * sin(0.5) * 0.5

#define MAXB  1024
#define CPAD  100096     // 391 * 256; pad rows stay zero (zero-init statics)
#define DFIX  512
#define NYMAX 1024
#define LOOKAHEAD 64     // groups; > max groups resident per wave (37)

// fp16, normalization-folded operands
__device__ __align__(256) __half g_Ah[MAXB * DFIX];   // S * a / ||a||
__device__ __align__(256) __half g_Wh[CPAD * DFIX];   // w / ||w||
__device__ unsigned g_cnt[NYMAX];                     // per-group arrive counters

// ---------------------------------------------------------------------------
// Fused prep kernel: block roles by blockIdx.x
//   [0, B)          : A rows  (smul = S)
//   [B, B+upfront)  : W rows  (smul = 1)
//   last block      : reset g_cnt
// ---------------------------------------------------------------------------
__global__ void prep_kernel(const float* __restrict__ A, const float* __restrict__ W,
                            int B, int upfront, int ny, int D)
{
    int bid = blockIdx.x;
    if (bid >= B + upfront) {                  // flags reset
        for (int i = threadIdx.x; i < ny; i += blockDim.x) g_cnt[i] = 0u;
        return;
    }
    const float* x;
    __half* dst;
    float smul;
    int row;
    if (bid < B) { row = bid;      x = A; dst = g_Ah; smul = S_SCALE; }
    else         { row = bid - B;  x = W; dst = g_Wh; smul = 1.0f;    }

    const float4* xv = reinterpret_cast<const float4*>(x + (size_t)row * (size_t)D);
    float4 v = xv[threadIdx.x];

    float s = v.x * v.x + v.y * v.y + v.z * v.z + v.w * v.w;
    #pragma unroll
    for (int off = 16; off > 0; off >>= 1)
        s += __shfl_down_sync(0xffffffffu, s, off);

    __shared__ float wsum[4];
    __shared__ float s_sc;
    int lane = threadIdx.x & 31, wid = threadIdx.x >> 5;
    if (lane == 0) wsum[wid] = s;
    __syncthreads();
    if (threadIdx.x == 0) {
        float t = wsum[0] + wsum[1] + wsum[2] + wsum[3];
        s_sc = smul / fmaxf(sqrtf(t), 1e-12f);
    }
    __syncthreads();
    float sc = s_sc;

    __half2 h01 = __floats2half2_rn(v.x * sc, v.y * sc);
    __half2 h23 = __floats2half2_rn(v.z * sc, v.w * sc);
    __half2* p = reinterpret_cast<__half2*>(dst + (size_t)row * (size_t)D) + threadIdx.x * 2;
    p[0] = h01;
    p[1] = h23;
}

// ---------------------------------------------------------------------------
// fp16 tensor-core GEMM (fp32 accumulate) + look-ahead W conversion.
// GEMM: CTA 128x128, BK=64, 8 warps (2m x 4n), warp tile 64x32, 2 CTAs/SM,
//   SW128 XOR swizzle + ldmatrix, 3-stage cp.async pipeline,
//   strength-reduced loader. (Round-10 body verbatim — best measured.)
// ---------------------------------------------------------------------------
#define BM 128
#define BN 128
#define BK 64
#define NTHREADS 256
#define A_TILE_BYTES (BM * 128)                      // 16384
#define B_TILE_BYTES (BN * 128)                      // 16384
#define STAGE_BYTES  (A_TILE_BYTES + B_TILE_BYTES)   // 32768
#define NSTAGE 3
#define SMEM_BYTES (NSTAGE * STAGE_BYTES)            // 98304

__device__ __forceinline__ void mma_f16(float* d, const uint32_t* a,
                                        uint32_t b0, uint32_t b1) {
    asm volatile(
        "mma.sync.aligned.m16n8k16.row.col.f32.f16.f16.f32 "
        "{%0,%1,%2,%3}, {%4,%5,%6,%7}, {%8,%9}, {%0,%1,%2,%3};"
        : "+f"(d[0]), "+f"(d[1]), "+f"(d[2]), "+f"(d[3])
        : "r"(a[0]), "r"(a[1]), "r"(a[2]), "r"(a[3]), "r"(b0), "r"(b1));
}

#define LDMATRIX_X4(r0, r1, r2, r3, addr)                                   \
    asm volatile("ldmatrix.sync.aligned.m8n8.x4.shared.b16 "                \
                 "{%0,%1,%2,%3}, [%4];"                                     \
                 : "=r"(r0), "=r"(r1), "=r"(r2), "=r"(r3) : "r"(addr))

__device__ __forceinline__ void cp_async16(uint32_t sm_dst, const void* g_src) {
    asm volatile("cp.async.cg.shared.global [%0], [%1], 16;"
                 :: "r"(sm_dst), "l"(g_src));
}

__global__ void __launch_bounds__(NTHREADS, 2)
arc_gemm_f16(const float* __restrict__ W, float* __restrict__ out,
             int C, int D, int ny)
{
    extern __shared__ char sm[];
    const uint32_t smaddr = (uint32_t)__cvta_generic_to_shared(sm);

    const int tid  = threadIdx.x;
    const int lane = tid & 31;
    const int warp = tid >> 5;
    const int y    = blockIdx.y;
    const int b0   = blockIdx.x * BM;
    const int c0   = y * BN;

    // ---- look-ahead W conversion: 16 rows of group y+LOOKAHEAD ----
    {
        int yt = y + LOOKAHEAD;
        if (yt < ny) {
            int rr = yt * BN + (int)blockIdx.x * 16 + (tid >> 4);
            int seg = tid & 15;
            if (rr < C) {
                const float4* src =
                    reinterpret_cast<const float4*>(W + (size_t)rr * (size_t)D);
                float4 v[8];
                #pragma unroll
                for (int q = 0; q < 8; q++) v[q] = src[seg + q * 16];
                float s = 0.0f;
                #pragma unroll
                for (int q = 0; q < 8; q++)
                    s += v[q].x * v[q].x + v[q].y * v[q].y
                       + v[q].z * v[q].z + v[q].w * v[q].w;
                #pragma unroll
                for (int off = 8; off > 0; off >>= 1)
                    s += __shfl_xor_sync(0xffffffffu, s, off);
                float rn = 1.0f / fmaxf(sqrtf(s), 1e-12f);
                uint2* dst = reinterpret_cast<uint2*>(g_Wh + (size_t)rr * (size_t)D);
                #pragma unroll
                for (int q = 0; q < 8; q++) {
                    __half2 h0 = __floats2half2_rn(v[q].x * rn, v[q].y * rn);
                    __half2 h1 = __floats2half2_rn(v[q].z * rn, v[q].w * rn);
                    uint2 u;
                    u.x = *reinterpret_cast<uint32_t*>(&h0);
                    u.y = *reinterpret_cast<uint32_t*>(&h1);
                    dst[seg + q * 16] = u;
                }
            }
            __syncthreads();
            if (tid == 0)
                asm volatile("red.release.gpu.global.add.u32 [%0], %1;"
                             :: "l"(&g_cnt[yt]), "r"(1u) : "memory");
        }
        if (y >= LOOKAHEAD) {
            if (tid == 0) {
                unsigned v = 0;
                do {
                    asm volatile("ld.acquire.gpu.global.u32 %0, [%1];"
                                 : "=r"(v) : "l"(&g_cnt[y]) : "memory");
                    if (v != 8u) __nanosleep(128);
                } while (v != 8u);
            }
            __syncthreads();
        }
    }

    // ---- GEMM body ----
    const int wm = (warp >> 2) * 64;   // 0, 64
    const int wn = (warp & 3) * 32;    // 0, 32, 64, 96
    const int r = lane >> 2;           // 0..7
    const int c = lane & 3;            // 0..3

    float acc[4][4][4];
    #pragma unroll
    for (int mi = 0; mi < 4; mi++)
        #pragma unroll
        for (int ni = 0; ni < 4; ni++)
            #pragma unroll
            for (int j = 0; j < 4; j++)
                acc[mi][ni][j] = 0.0f;

    const int nch = D / BK;   // 8

    // --- strength-reduced loader state ---
    const int rowL = tid >> 3;
    const int segL = tid & 7;
    const uint32_t swzL = (((uint32_t)segL << 4) ^ (((uint32_t)rowL & 7) << 4));
    const uint32_t smoffA = (uint32_t)rowL * 128 + swzL;
    const uint32_t smoffB = A_TILE_BYTES + smoffA;
    const char* gA = (const char*)g_Ah + (size_t)(b0 + rowL) * 1024 + segL * 16;
    const char* gB = (const char*)g_Wh + (size_t)(c0 + rowL) * 1024 + segL * 16;

    auto load_chunk = [&](int ch, int st) {
        uint32_t stage = smaddr + st * STAGE_BYTES;
        const char* ga = gA + ch * 128;
        uint32_t sa = stage + smoffA;
        #pragma unroll
        for (int h = 0; h < 4; h++) {
            cp_async16(sa, ga);
            sa += 32 * 128;
            ga += 32 * 1024;
        }
        const char* gb = gB + ch * 128;
        uint32_t sb = stage + smoffB;
        #pragma unroll
        for (int h = 0; h < 4; h++) {
            cp_async16(sb, gb);
            sb += 32 * 128;
            gb += 32 * 1024;
        }
        asm volatile("cp.async.commit_group;" ::: "memory");
    };

    // ldmatrix per-thread addressing (SW128 swizzle)
    const int lane15 = lane & 15;
    const uint32_t kq16 = ((lane >> 4) & 1) << 4;
    const uint32_t sw = (uint32_t)(lane15 & 7) << 4;
    uint32_t relA[4], relB[2];
    #pragma unroll
    for (int t = 0; t < 4; t++)
        relA[t] = (uint32_t)(wm + t * 16 + lane15) * 128;
    #pragma unroll
    for (int t = 0; t < 2; t++)
        relB[t] = A_TILE_BYTES + (uint32_t)(wn + t * 16 + lane15) * 128;

    load_chunk(0, 0);
    load_chunk(1, 1);

    for (int i = 0; i < nch; i++) {
        if (i + 1 < nch)
            asm volatile("cp.async.wait_group 1;" ::: "memory");
        else
            asm volatile("cp.async.wait_group 0;" ::: "memory");
        __syncthreads();

        if (i + 2 < nch)
            load_chunk(i + 2, (i + 2) % NSTAGE);

        uint32_t stage = smaddr + (i % NSTAGE) * STAGE_BYTES;

        #pragma unroll
        for (int ks = 0; ks < 4; ks++) {
            uint32_t kx = (((uint32_t)ks << 5) + kq16) ^ sw;

            uint32_t af[4][4];
            #pragma unroll
            for (int mt = 0; mt < 4; mt++)
                LDMATRIX_X4(af[mt][0], af[mt][1], af[mt][2], af[mt][3],
                            stage + relA[mt] + kx);

            uint32_t bf[2][4];
            #pragma unroll
            for (int nt = 0; nt < 2; nt++)
                LDMATRIX_X4(bf[nt][0], bf[nt][1], bf[nt][2], bf[nt][3],
                            stage + relB[nt] + kx);

            #pragma unroll
            for (int mt = 0; mt < 4; mt++)
                #pragma unroll
                for (int nt = 0; nt < 2; nt++) {
                    mma_f16(acc[mt][nt * 2 + 0], af[mt], bf[nt][0], bf[nt][2]);
                    mma_f16(acc[mt][nt * 2 + 1], af[mt], bf[nt][1], bf[nt][3]);
                }
        }
        __syncthreads();
    }

    // epilogue: bare stores (all scaling folded into operands)
    #pragma unroll
    for (int ni = 0; ni < 4; ni++) {
        int cc = c0 + wn + ni * 8 + 2 * c;
        if (cc < C) {
            #pragma unroll
            for (int mi = 0; mi < 4; mi++) {
                #pragma unroll
                for (int h = 0; h < 2; h++) {
                    int row = b0 + wm + mi * 16 + h * 8 + r;
                    float2 v = make_float2(acc[mi][ni][h * 2 + 0],
                                           acc[mi][ni][h * 2 + 1]);
                    *reinterpret_cast<float2*>(out + (size_t)row * (size_t)C + cc) = v;
                }
            }
        }
    }
}

// ---------------------------------------------------------------------------
// Fixup: margin at label columns only (separate tiny kernel).
// ---------------------------------------------------------------------------
__global__ void fixup_kernel(const int* __restrict__ label, float* __restrict__ out,
                             int B, int C)
{
    int b = blockIdx.x * blockDim.x + threadIdx.x;
    if (b >= B) return;
    int c = label[b];
    if (c < 0 || c >= C) return;
    size_t idx = (size_t)b * (size_t)C + (size_t)c;
    float cosv = out[idx] * INV_S;
    float s2 = 1.0f - cosv * cosv;
    s2 = fminf(fmaxf(s2, 0.0f), 1.0f);
    float sine = sqrtf(s2);
    float phi = cosv * COS_M_C - sine * SIN_M_C;
    phi = (cosv > TH_C) ? phi : (cosv - MM_C);
    out[idx] = phi * S_SCALE;
}

// ---------------------------------------------------------------------------
// Launch
// ---------------------------------------------------------------------------
extern "C" void kernel_launch(void* const* d_in, const int* in_sizes, int n_in,
                              void* d_out, int out_size)
{
    const float* input  = (const float*)d_in[0];   // [B, D]
    const int*   label  = (const int*)  d_in[1];   // [B]
    const float* weight = (const float*)d_in[2];   // [C, D]
    float* out = (float*)d_out;                    // [B, C]

    const int B = in_sizes[1];
    const int D = in_sizes[0] / B;
    const int C = in_sizes[2] / D;
    const int ny = (C + BN - 1) / BN;

    cudaFuncSetAttribute(arc_gemm_f16, cudaFuncAttributeMaxDynamicSharedMemorySize,
                         SMEM_BYTES);

    int upfront = LOOKAHEAD * BN;
    if (upfront > C) upfront = C;

    // 1) fused prep: flags reset + A rows + upfront W rows (one launch)
    prep_kernel<<<B + upfront + 1, 128>>>(input, weight, B, upfront, ny, D);

    // 2) GEMM with look-ahead W conversion (m-fast grid -> 8x L2 reuse)
    dim3 grid(B / BM, ny);
    arc_gemm_f16<<<grid, NTHREADS, SMEM_BYTES>>>(weight, out, C, D, ny);

    // 3) margin fixup at label columns
    fixup_kernel<<<(B + 127) / 128, 128>>>(label, out, B, C);
}

// round 16
// speedup vs baseline: 1.5391x; 1.0016x over previous
#include <cuda_runtime.h>
#include <cuda_fp16.h>
#include <math.h>
#include <stdint.h>

// ---------------------------------------------------------------------------
// ArcMarginProduct constants (S=30, M=0.5)
// ---------------------------------------------------------------------------
#define S_SCALE   30.0f
#define INV_S     (1.0f / 30.0f)
#define COS_M_C   0.87758256189037271612f   // cos(0.5)
#define SIN_M_C   0.47942553860420300027f   // sin(0.5)
#define TH_C     (-0.87758256189037271612f) // cos(pi - 0.5)
#define MM_C      7.19138307906304500405f   // S * sin(0.5) * 0.5

#define MAXB  1024
#define CPAD  100096     // 391 * 256; pad rows stay zero (zero-init statics)
#define DFIX  512
#define NYMAX 1024
#define LOOKAHEAD 64     // groups; > max groups resident per wave (37)

// fp16, normalization-folded operands
__device__ __align__(256) __half g_Ah[MAXB * DFIX];   // S * a / ||a||
__device__ __align__(256) __half g_Wh[CPAD * DFIX];   // w / ||w||
__device__ unsigned g_cnt[NYMAX];                     // per-group arrive counters

// ---------------------------------------------------------------------------
// Fused prep kernel: block roles by blockIdx.x
//   [0, B)          : A rows  (smul = S)
//   [B, B+upfront)  : W rows  (smul = 1)
//   last block      : reset g_cnt
// ---------------------------------------------------------------------------
__global__ void prep_kernel(const float* __restrict__ A, const float* __restrict__ W,
                            int B, int upfront, int ny, int D)
{
    int bid = blockIdx.x;
    if (bid >= B + upfront) {                  // flags reset
        for (int i = threadIdx.x; i < ny; i += blockDim.x) g_cnt[i] = 0u;
        return;
    }
    const float* x;
    __half* dst;
    float smul;
    int row;
    if (bid < B) { row = bid;      x = A; dst = g_Ah; smul = S_SCALE; }
    else         { row = bid - B;  x = W; dst = g_Wh; smul = 1.0f;    }

    const float4* xv = reinterpret_cast<const float4*>(x + (size_t)row * (size_t)D);
    float4 v = xv[threadIdx.x];

    float s = v.x * v.x + v.y * v.y + v.z * v.z + v.w * v.w;
    #pragma unroll
    for (int off = 16; off > 0; off >>= 1)
        s += __shfl_down_sync(0xffffffffu, s, off);

    __shared__ float wsum[4];
    __shared__ float s_sc;
    int lane = threadIdx.x & 31, wid = threadIdx.x >> 5;
    if (lane == 0) wsum[wid] = s;
    __syncthreads();
    if (threadIdx.x == 0) {
        float t = wsum[0] + wsum[1] + wsum[2] + wsum[3];
        s_sc = smul / fmaxf(sqrtf(t), 1e-12f);
    }
    __syncthreads();
    float sc = s_sc;

    __half2 h01 = __floats2half2_rn(v.x * sc, v.y * sc);
    __half2 h23 = __floats2half2_rn(v.z * sc, v.w * sc);
    __half2* p = reinterpret_cast<__half2*>(dst + (size_t)row * (size_t)D) + threadIdx.x * 2;
    p[0] = h01;
    p[1] = h23;
}

// ---------------------------------------------------------------------------
// fp16 tensor-core GEMM (fp32 accumulate) + look-ahead W conversion +
// patch-after-store margin fixup (post-epilogue, codegen-safe).
// GEMM: CTA 128x128, BK=64, 8 warps (2m x 4n), warp tile 64x32, 2 CTAs/SM,
//   SW128 XOR swizzle + ldmatrix, 3-stage cp.async pipeline,
//   strength-reduced loader. (Round-10 body verbatim — best measured.)
// ---------------------------------------------------------------------------
#define BM 128
#define BN 128
#define BK 64
#define NTHREADS 256
#define A_TILE_BYTES (BM * 128)                      // 16384
#define B_TILE_BYTES (BN * 128)                      // 16384
#define STAGE_BYTES  (A_TILE_BYTES + B_TILE_BYTES)   // 32768
#define NSTAGE 3
#define SMEM_BYTES (NSTAGE * STAGE_BYTES)            // 98304

__device__ __forceinline__ void mma_f16(float* d, const uint32_t* a,
                                        uint32_t b0, uint32_t b1) {
    asm volatile(
        "mma.sync.aligned.m16n8k16.row.col.f32.f16.f16.f32 "
        "{%0,%1,%2,%3}, {%4,%5,%6,%7}, {%8,%9}, {%0,%1,%2,%3};"
        : "+f"(d[0]), "+f"(d[1]), "+f"(d[2]), "+f"(d[3])
        : "r"(a[0]), "r"(a[1]), "r"(a[2]), "r"(a[3]), "r"(b0), "r"(b1));
}

#define LDMATRIX_X4(r0, r1, r2, r3, addr)                                   \
    asm volatile("ldmatrix.sync.aligned.m8n8.x4.shared.b16 "                \
                 "{%0,%1,%2,%3}, [%4];"                                     \
                 : "=r"(r0), "=r"(r1), "=r"(r2), "=r"(r3) : "r"(addr))

__device__ __forceinline__ void cp_async16(uint32_t sm_dst, const void* g_src) {
    asm volatile("cp.async.cg.shared.global [%0], [%1], 16;"
                 :: "r"(sm_dst), "l"(g_src));
}

__global__ void __launch_bounds__(NTHREADS, 2)
arc_gemm_f16(const float* __restrict__ W, const int* __restrict__ label,
             float* __restrict__ out, int C, int D, int ny, int B)
{
    extern __shared__ char sm[];
    const uint32_t smaddr = (uint32_t)__cvta_generic_to_shared(sm);

    const int tid  = threadIdx.x;
    const int lane = tid & 31;
    const int warp = tid >> 5;
    const int y    = blockIdx.y;
    const int b0   = blockIdx.x * BM;
    const int c0   = y * BN;

    // ---- look-ahead W conversion: 16 rows of group y+LOOKAHEAD ----
    {
        int yt = y + LOOKAHEAD;
        if (yt < ny) {
            int rr = yt * BN + (int)blockIdx.x * 16 + (tid >> 4);
            int seg = tid & 15;
            if (rr < C) {
                const float4* src =
                    reinterpret_cast<const float4*>(W + (size_t)rr * (size_t)D);
                float4 v[8];
                #pragma unroll
                for (int q = 0; q < 8; q++) v[q] = src[seg + q * 16];
                float s = 0.0f;
                #pragma unroll
                for (int q = 0; q < 8; q++)
                    s += v[q].x * v[q].x + v[q].y * v[q].y
                       + v[q].z * v[q].z + v[q].w * v[q].w;
                #pragma unroll
                for (int off = 8; off > 0; off >>= 1)
                    s += __shfl_xor_sync(0xffffffffu, s, off);
                float rn = 1.0f / fmaxf(sqrtf(s), 1e-12f);
                uint2* dst = reinterpret_cast<uint2*>(g_Wh + (size_t)rr * (size_t)D);
                #pragma unroll
                for (int q = 0; q < 8; q++) {
                    __half2 h0 = __floats2half2_rn(v[q].x * rn, v[q].y * rn);
                    __half2 h1 = __floats2half2_rn(v[q].z * rn, v[q].w * rn);
                    uint2 u;
                    u.x = *reinterpret_cast<uint32_t*>(&h0);
                    u.y = *reinterpret_cast<uint32_t*>(&h1);
                    dst[seg + q * 16] = u;
                }
            }
            __syncthreads();
            if (tid == 0)
                asm volatile("red.release.gpu.global.add.u32 [%0], %1;"
                             :: "l"(&g_cnt[yt]), "r"(1u) : "memory");
        }
        if (y >= LOOKAHEAD) {
            if (tid == 0) {
                unsigned v = 0;
                do {
                    asm volatile("ld.acquire.gpu.global.u32 %0, [%1];"
                                 : "=r"(v) : "l"(&g_cnt[y]) : "memory");
                    if (v != 8u) __nanosleep(128);
                } while (v != 8u);
            }
            __syncthreads();
        }
    }

    // ---- GEMM body (round-10 config) ----
    const int wm = (warp >> 2) * 64;   // 0, 64
    const int wn = (warp & 3) * 32;    // 0, 32, 64, 96
    const int r = lane >> 2;           // 0..7
    const int c = lane & 3;            // 0..3

    float acc[4][4][4];
    #pragma unroll
    for (int mi = 0; mi < 4; mi++)
        #pragma unroll
        for (int ni = 0; ni < 4; ni++)
            #pragma unroll
            for (int j = 0; j < 4; j++)
                acc[mi][ni][j] = 0.0f;

    const int nch = D / BK;   // 8

    // --- strength-reduced loader state ---
    const int rowL = tid >> 3;
    const int segL = tid & 7;
    const uint32_t swzL = (((uint32_t)segL << 4) ^ (((uint32_t)rowL & 7) << 4));
    const uint32_t smoffA = (uint32_t)rowL * 128 + swzL;
    const uint32_t smoffB = A_TILE_BYTES + smoffA;
    const char* gA = (const char*)g_Ah + (size_t)(b0 + rowL) * 1024 + segL * 16;
    const char* gB = (const char*)g_Wh + (size_t)(c0 + rowL) * 1024 + segL * 16;

    auto load_chunk = [&](int ch, int st) {
        uint32_t stage = smaddr + st * STAGE_BYTES;
        const char* ga = gA + ch * 128;
        uint32_t sa = stage + smoffA;
        #pragma unroll
        for (int h = 0; h < 4; h++) {
            cp_async16(sa, ga);
            sa += 32 * 128;
            ga += 32 * 1024;
        }
        const char* gb = gB + ch * 128;
        uint32_t sb = stage + smoffB;
        #pragma unroll
        for (int h = 0; h < 4; h++) {
            cp_async16(sb, gb);
            sb += 32 * 128;
            gb += 32 * 1024;
        }
        asm volatile("cp.async.commit_group;" ::: "memory");
    };

    // ldmatrix per-thread addressing (SW128 swizzle)
    const int lane15 = lane & 15;
    const uint32_t kq16 = ((lane >> 4) & 1) << 4;
    const uint32_t sw = (uint32_t)(lane15 & 7) << 4;
    uint32_t relA[4], relB[2];
    #pragma unroll
    for (int t = 0; t < 4; t++)
        relA[t] = (uint32_t)(wm + t * 16 + lane15) * 128;
    #pragma unroll
    for (int t = 0; t < 2; t++)
        relB[t] = A_TILE_BYTES + (uint32_t)(wn + t * 16 + lane15) * 128;

    load_chunk(0, 0);
    load_chunk(1, 1);

    for (int i = 0; i < nch; i++) {
        if (i + 1 < nch)
            asm volatile("cp.async.wait_group 1;" ::: "memory");
        else
            asm volatile("cp.async.wait_group 0;" ::: "memory");
        __syncthreads();

        if (i + 2 < nch)
            load_chunk(i + 2, (i + 2) % NSTAGE);

        uint32_t stage = smaddr + (i % NSTAGE) * STAGE_BYTES;

        #pragma unroll
        for (int ks = 0; ks < 4; ks++) {
            uint32_t kx = (((uint32_t)ks << 5) + kq16) ^ sw;

            uint32_t af[4][4];
            #pragma unroll
            for (int mt = 0; mt < 4; mt++)
                LDMATRIX_X4(af[mt][0], af[mt][1], af[mt][2], af[mt][3],
                            stage + relA[mt] + kx);

            uint32_t bf[2][4];
            #pragma unroll
            for (int nt = 0; nt < 2; nt++)
                LDMATRIX_X4(bf[nt][0], bf[nt][1], bf[nt][2], bf[nt][3],
                            stage + relB[nt] + kx);

            #pragma unroll
            for (int mt = 0; mt < 4; mt++)
                #pragma unroll
                for (int nt = 0; nt < 2; nt++) {
                    mma_f16(acc[mt][nt * 2 + 0], af[mt], bf[nt][0], bf[nt][2]);
                    mma_f16(acc[mt][nt * 2 + 1], af[mt], bf[nt][1], bf[nt][3]);
                }
        }
        __syncthreads();
    }

    // epilogue: bare stores (all scaling folded into operands) — untouched
    #pragma unroll
    for (int ni = 0; ni < 4; ni++) {
        int cc = c0 + wn + ni * 8 + 2 * c;
        if (cc < C) {
            #pragma unroll
            for (int mi = 0; mi < 4; mi++) {
                #pragma unroll
                for (int h = 0; h < 2; h++) {
                    int row = b0 + wm + mi * 16 + h * 8 + r;
                    float2 v = make_float2(acc[mi][ni][h * 2 + 0],
                                           acc[mi][ni][h * 2 + 1]);
                    *reinterpret_cast<float2*>(out + (size_t)row * (size_t)C + cc) = v;
                }
            }
        }
    }

    // ---- patch-after-store margin fixup (this CTA's label hits only) ----
    __syncthreads();   // CTA-scope fence: epilogue stores visible to all threads
    if (tid < BM) {
        int b = b0 + tid;
        if (b < B) {
            int lab = label[b];
            if (lab >= c0 && lab < c0 + BN && lab < C) {
                size_t idx = (size_t)b * (size_t)C + (size_t)lab;
                float cosv = __ldcg(out + idx) * INV_S;   // L2 read (L1-bypass)
                float s2 = 1.0f - cosv * cosv;
                s2 = fminf(fmaxf(s2, 0.0f), 1.0f);
                float phi = cosv * COS_M_C - sqrtf(s2) * SIN_M_C;
                phi = (cosv > TH_C) ? phi : (cosv - MM_C);
                out[idx] = phi * S_SCALE;
            }
        }
    }
}

// ---------------------------------------------------------------------------
// Launch
// ---------------------------------------------------------------------------
extern "C" void kernel_launch(void* const* d_in, const int* in_sizes, int n_in,
                              void* d_out, int out_size)
{
    const float* input  = (const float*)d_in[0];   // [B, D]
    const int*   label  = (const int*)  d_in[1];   // [B]
    const float* weight = (const float*)d_in[2];   // [C, D]
    float* out = (float*)d_out;                    // [B, C]

    const int B = in_sizes[1];
    const int D = in_sizes[0] / B;
    const int C = in_sizes[2] / D;
    const int ny = (C + BN - 1) / BN;

    cudaFuncSetAttribute(arc_gemm_f16, cudaFuncAttributeMaxDynamicSharedMemorySize,
                         SMEM_BYTES);

    int upfront = LOOKAHEAD * BN;
    if (upfront > C) upfront = C;

    // 1) fused prep: flags reset + A rows + upfront W rows (one launch)
    prep_kernel<<<B + upfront + 1, 128>>>(input, weight, B, upfront, ny, D);

    // 2) GEMM with look-ahead W conversion + patch-after-store fixup
    dim3 grid(B / BM, ny);
    arc_gemm_f16<<<grid, NTHREADS, SMEM_BYTES>>>(weight, label, out, C, D, ny, B);
}